// round 6
// baseline (speedup 1.0000x reference)
#include <cuda_runtime.h>
#include <cuda_fp16.h>
#include <cstdint>

// ===========================================================================
// Fused LSTM cell, single-kernel mma.sync, barrier-free main loop.
// Weights pre-arranged in gmem in per-lane MMA fragment order -> each thread
// LDGs its B fragments directly (coalesced, L1/L2-resident); A (xh) fragments
// loaded straight from gmem into registers. NO smem staging for GEMM1, no
// cp.async, no barriers until the fused output GEMM (h tile in smem).
// CTA = 64 rows, 8 warps = 4(M) x 2(N), warp tile 16x32. 2 CTAs/SM.
// d_out = [c | h | y], each B*128 fp32.
// ===========================================================================

__device__ uint2 g_Wfrag[8 * 16 * 8 * 32];    // [chunk][ks][tile][lane] 256KB
__device__ uint2 g_WoutFrag[8 * 16 * 32];     // [ks][tile][lane]        32KB

// --------------------------------------------------------------------------
// K0: build fragment-ordered weights.
// Gates: chunk c covers gate-cols [c*16, c*16+16); tile tt (0..7):
//   warpN = tt>>2, gate = tt&3; fragment element for lane l:
//   n = (lane>>2)  -> gate-col gc = c*16 + warpN*8 + (lane>>2)
//   k = ks*16 + (lane&3)*2  (+1, +8, +9)
// --------------------------------------------------------------------------
__global__ void prep_weights(const float* __restrict__ w,  const float* __restrict__ wi,
                             const float* __restrict__ wf, const float* __restrict__ wo,
                             const float* __restrict__ w_out)
{
    const int stride = gridDim.x * blockDim.x;
    for (int idx = blockIdx.x * blockDim.x + threadIdx.x; idx < 32768; idx += stride) {
        int lane = idx & 31, tt = (idx >> 5) & 7, ks = (idx >> 8) & 15, c = idx >> 12;
        int gate = tt & 3;
        int gc = c * 16 + (tt >> 2) * 8 + (lane >> 2);
        int k  = ks * 16 + (lane & 3) * 2;
        const float* src = (gate == 0) ? w : (gate == 1) ? wi : (gate == 2) ? wf : wo;
        const float* p = src + gc * 256 + k;
        __half2 e0 = __floats2half2_rn(p[0], p[1]);
        __half2 e1 = __floats2half2_rn(p[8], p[9]);
        uint2 v; v.x = *(uint32_t*)&e0; v.y = *(uint32_t*)&e1;
        g_Wfrag[idx] = v;
    }
    for (int idx = blockIdx.x * blockDim.x + threadIdx.x; idx < 4096; idx += stride) {
        int lane = idx & 31, tt = (idx >> 5) & 15, ks = idx >> 9;
        int n = tt * 8 + (lane >> 2);
        int k = ks * 16 + (lane & 3) * 2;
        const float* p = w_out + n * 128 + k;
        __half2 e0 = __floats2half2_rn(p[0], p[1]);
        __half2 e1 = __floats2half2_rn(p[8], p[9]);
        uint2 v; v.x = *(uint32_t*)&e0; v.y = *(uint32_t*)&e1;
        g_WoutFrag[idx] = v;
    }
}

// --------------------------------------------------------------------------
// helpers
// --------------------------------------------------------------------------
__device__ __forceinline__ void ldsm_x4(uint32_t addr, uint32_t& r0, uint32_t& r1,
                                        uint32_t& r2, uint32_t& r3)
{
    asm volatile("ldmatrix.sync.aligned.m8n8.x4.shared.b16 {%0,%1,%2,%3}, [%4];"
                 : "=r"(r0), "=r"(r1), "=r"(r2), "=r"(r3) : "r"(addr));
}
__device__ __forceinline__ void mma16816(float* c, const uint32_t* a, uint32_t b0, uint32_t b1)
{
    asm volatile(
        "mma.sync.aligned.m16n8k16.row.col.f32.f16.f16.f32 "
        "{%0,%1,%2,%3},{%4,%5,%6,%7},{%8,%9},{%0,%1,%2,%3};"
        : "+f"(c[0]), "+f"(c[1]), "+f"(c[2]), "+f"(c[3])
        : "r"(a[0]), "r"(a[1]), "r"(a[2]), "r"(a[3]), "r"(b0), "r"(b1));
}
__device__ __forceinline__ float tanha(float x) {
    float y; asm("tanh.approx.f32 %0, %1;" : "=f"(y) : "f"(x)); return y;
}
__device__ __forceinline__ float2 sig2(float a, float b) {
    __half2 u = __floats2half2_rn(0.5f * a, 0.5f * b);
    uint32_t uin = *(uint32_t*)&u, r;
    asm("tanh.approx.f16x2 %0, %1;" : "=r"(r) : "r"(uin));
    __half2 t = *(__half2*)&r;
    float2 o;
    o.x = fmaf(__half2float(t.x), 0.5f, 0.5f);
    o.y = fmaf(__half2float(t.y), 0.5f, 0.5f);
    return o;
}
// 256B-row smem tile (128 halves), XOR swizzle
__device__ __forceinline__ uint32_t swz256(int r, int seg) {   // seg = 16B unit, 0..15
    return (uint32_t)(r * 256 + ((seg ^ (r & 7)) << 4));
}
__device__ __forceinline__ uint32_t packh2(float a, float b) {
    __half2 h = __floats2half2_rn(a, b);
    return *(uint32_t*)&h;
}

#define HT_OFF   0
#define SMEM_TOT 16384

extern __shared__ char smem[];

// --------------------------------------------------------------------------
// Fused kernel. 256 threads = 8 warps in 4(M) x 2(N); warp tile 16x32.
// --------------------------------------------------------------------------
__global__ __launch_bounds__(256, 2) void lstm_fused(
    const float* __restrict__ x, const float* __restrict__ h_,
    const float* __restrict__ c_,
    const float* __restrict__ bz, const float* __restrict__ bi,
    const float* __restrict__ bf, const float* __restrict__ bo,
    const float* __restrict__ bout,
    float* __restrict__ outC, float* __restrict__ outH, float* __restrict__ outY)
{
    const int tid  = threadIdx.x, lane = tid & 31;
    const int warp = tid >> 5;
    const int warpM = warp >> 1, warpN = warp & 1;
    const int row0 = blockIdx.x * 64;

    const uint32_t sbase = (uint32_t)__cvta_generic_to_shared(smem);

    // ---- A fragments straight from gmem into registers ----
    // a0=(r,q..q+1) a1=(r+8,q) a2=(r,q+8) a3=(r+8,q+8); ks<8 -> x, ks>=8 -> h_
    const int arow = row0 + warpM * 16 + (lane >> 2);
    const int q    = (lane & 3) * 2;
    uint32_t afr[16][4];
    #pragma unroll
    for (int ks = 0; ks < 16; ks++) {
        const float* base = (ks < 8) ? x : h_;
        const int col = (ks & 7) * 16 + q;
        const float* p0 = base + (size_t)arow * 128 + col;
        const float* p1 = base + (size_t)(arow + 8) * 128 + col;
        float2 f00 = *(const float2*)p0;
        float2 f01 = *(const float2*)p1;
        float2 f10 = *(const float2*)(p0 + 8);
        float2 f11 = *(const float2*)(p1 + 8);
        afr[ks][0] = packh2(f00.x, f00.y);
        afr[ks][1] = packh2(f01.x, f01.y);
        afr[ks][2] = packh2(f10.x, f10.y);
        afr[ks][3] = packh2(f11.x, f11.y);
    }

    // =================== GEMM1 + LSTM epilogue, 8 chunks (no barriers) =====
    const uint2* __restrict__ wfbase = g_Wfrag + warpN * 128 + lane;
    #pragma unroll
    for (int c = 0; c < 8; c++) {
        float acc[4][4];
        #pragma unroll
        for (int nt = 0; nt < 4; nt++)
            #pragma unroll
            for (int r = 0; r < 4; r++) acc[nt][r] = 0.f;

        #pragma unroll
        for (int ks = 0; ks < 16; ks++) {
            const uint2* bp = wfbase + (c * 16 + ks) * 256;
            uint2 b0 = __ldg(bp);
            uint2 b1 = __ldg(bp + 32);
            uint2 b2 = __ldg(bp + 64);
            uint2 b3 = __ldg(bp + 96);
            mma16816(acc[0], afr[ks], b0.x, b0.y);   // z
            mma16816(acc[1], afr[ks], b1.x, b1.y);   // i
            mma16816(acc[2], afr[ks], b2.x, b2.y);   // f
            mma16816(acc[3], afr[ks], b3.x, b3.y);   // o
        }

        // ---- register-only LSTM epilogue: 16 gate-cols of this chunk ----
        const int colb = c * 16 + warpN * 8 + 2 * (lane & 3);
        const float2 vz = __ldg((const float2*)(bz + colb));
        const float2 vi = __ldg((const float2*)(bi + colb));
        const float2 vf = __ldg((const float2*)(bf + colb));
        const float2 vo = __ldg((const float2*)(bo + colb));
        const int hseg = c * 2 + warpN;
        #pragma unroll
        for (int rh = 0; rh < 2; rh++) {
            const int rloc = warpM * 16 + (lane >> 2) + rh * 8;
            const int row  = row0 + rloc;
            const float2 cold = __ldg((const float2*)(c_ + (size_t)row * 128 + colb));

            float gz0 = acc[0][rh * 2 + 0] + vz.x, gz1 = acc[0][rh * 2 + 1] + vz.y;
            float gi0 = acc[1][rh * 2 + 0] + vi.x, gi1 = acc[1][rh * 2 + 1] + vi.y;
            float gf0 = acc[2][rh * 2 + 0] + vf.x, gf1 = acc[2][rh * 2 + 1] + vf.y;
            float go0 = acc[3][rh * 2 + 0] + vo.x, go1 = acc[3][rh * 2 + 1] + vo.y;

            float2 si = sig2(gi0, gi1);
            float2 sf = sig2(gf0, gf1);
            float2 so = sig2(go0, go1);
            float z0 = tanha(gz0), z1 = tanha(gz1);
            float c0 = fmaf(sf.x, cold.x, si.x * z0);
            float c1 = fmaf(sf.y, cold.y, si.y * z1);
            float h0 = so.x * tanha(c0);
            float h1 = so.y * tanha(c1);

            *(float2*)(outC + (size_t)row * 128 + colb) = make_float2(c0, c1);
            *(float2*)(outH + (size_t)row * 128 + colb) = make_float2(h0, h1);
            *(__half2*)(smem + HT_OFF + swz256(rloc, hseg) + (colb & 7) * 2) =
                __floats2half2_rn(h0, h1);
        }
    }

    __syncthreads();   // h tile complete

    // =================== GEMM2: y = sigmoid(h @ w_out^T + b_out) ==========
    const int a_row  = warpM * 16 + (lane & 15);
    const int a_segk = lane >> 4;

    float acc2[8][4];
    #pragma unroll
    for (int nt = 0; nt < 8; nt++)
        #pragma unroll
        for (int r = 0; r < 4; r++) acc2[nt][r] = 0.f;

    const uint32_t ht0 = sbase + HT_OFF;
    const uint2* __restrict__ wobase = g_WoutFrag + warpN * 256 + lane;
    #pragma unroll
    for (int ks = 0; ks < 8; ks++) {
        uint32_t a[4];
        ldsm_x4(ht0 + swz256(a_row, ks * 2 + a_segk), a[0], a[1], a[2], a[3]);
        const uint2* bp = wobase + ks * 512;
        #pragma unroll
        for (int nt = 0; nt < 8; nt++) {
            uint2 bv = __ldg(bp + nt * 32);
            mma16816(acc2[nt], a, bv.x, bv.y);
        }
    }

    #pragma unroll
    for (int nt = 0; nt < 8; nt++) {
        const int col = warpN * 64 + nt * 8 + 2 * (lane & 3);
        const float2 vb = __ldg((const float2*)(bout + col));
        #pragma unroll
        for (int rh = 0; rh < 2; rh++) {
            const int row = row0 + warpM * 16 + (lane >> 2) + rh * 8;
            float2 v = sig2(acc2[nt][rh * 2 + 0] + vb.x,
                            acc2[nt][rh * 2 + 1] + vb.y);
            *(float2*)(outY + (size_t)row * 128 + col) = v;
        }
    }
}

// --------------------------------------------------------------------------
// Launch
// --------------------------------------------------------------------------
extern "C" void kernel_launch(void* const* d_in, const int* in_sizes, int n_in,
                              void* d_out, int out_size)
{
    const float* c_    = (const float*)d_in[0];
    const float* h_    = (const float*)d_in[1];
    const float* x     = (const float*)d_in[2];
    const float* w     = (const float*)d_in[3];
    const float* wi    = (const float*)d_in[4];
    const float* wf    = (const float*)d_in[5];
    const float* wo    = (const float*)d_in[6];
    const float* w_out = (const float*)d_in[7];
    const float* b     = (const float*)d_in[8];
    const float* bi    = (const float*)d_in[9];
    const float* bf    = (const float*)d_in[10];
    const float* bo    = (const float*)d_in[11];
    const float* b_out = (const float*)d_in[12];

    const int B = in_sizes[0] / 128;
    const size_t BC = (size_t)B * 128;
    float* outC = (float*)d_out;
    float* outH = outC + BC;
    float* outY = outH + BC;

    cudaFuncSetAttribute(lstm_fused, cudaFuncAttributeMaxDynamicSharedMemorySize, SMEM_TOT);

    prep_weights<<<64, 256>>>(w, wi, wf, wo, w_out);
    lstm_fused<<<B / 64, 256, SMEM_TOT>>>(x, h_, c_, b, bi, bf, bo, b_out,
                                          outC, outH, outY);
}

// round 7
// speedup vs baseline: 1.3427x; 1.3427x over previous
#include <cuda_runtime.h>
#include <cuda_fp16.h>
#include <cstdint>

// ===========================================================================
// Fused LSTM cell, single-kernel mma.sync, 2 CTAs/SM, software-pipelined
// epilogue: epilogue of chunk c-1 executes in the cp.async-arrival shadow of
// chunk c+1, so MUFU/store bursts overlap memory latency instead of sitting
// between barriers. A (xh) fragments register-resident. Sigmoids + z-tanh on
// the f16x2 MUFU path; tanh(c) stays f32.
// d_out = [c | h | y], each B*128 fp32.
// ===========================================================================

#define AS_OFF    0
#define BS_OFF(i) (32768 + (i) * 32768)
#define HT_OFF    98304
#define SMEM_TOT  114688

__device__ __half g_W16r[512 * 256];    // gate-interleaved stacked weights, fp16
__device__ __half g_wout16[128 * 128];  // w_out, fp16

// --------------------------------------------------------------------------
// K0: convert weights. N-chunks of 64 rows:
//   chunk k (0..7): rows = [warpN0: z(8),i(8),f(8),o(8) | warpN1: same]
//   row r: grp=r>>5, gate=(r>>3)&3, sub=r&7 -> gate-col = k*16 + grp*8 + sub
// --------------------------------------------------------------------------
__global__ void prep_weights(const float* __restrict__ w,  const float* __restrict__ wi,
                             const float* __restrict__ wf, const float* __restrict__ wo,
                             const float* __restrict__ w_out)
{
    for (int idx = blockIdx.x * blockDim.x + threadIdx.x; idx < 512 * 256;
         idx += gridDim.x * blockDim.x) {
        int dstrow = idx >> 8, kk = idx & 255;
        int chunk = dstrow >> 6, r = dstrow & 63;
        int grp = r >> 5, gate = (r >> 3) & 3, sub = r & 7;
        int gc = chunk * 16 + grp * 8 + sub;
        const float* src = (gate == 0) ? w : (gate == 1) ? wi : (gate == 2) ? wf : wo;
        g_W16r[idx] = __float2half_rn(src[gc * 256 + kk]);
    }
    for (int idx = blockIdx.x * blockDim.x + threadIdx.x; idx < 128 * 128;
         idx += gridDim.x * blockDim.x)
        g_wout16[idx] = __float2half_rn(w_out[idx]);
}

// --------------------------------------------------------------------------
// helpers
// --------------------------------------------------------------------------
__device__ __forceinline__ void ldsm_x4(uint32_t addr, uint32_t& r0, uint32_t& r1,
                                        uint32_t& r2, uint32_t& r3)
{
    asm volatile("ldmatrix.sync.aligned.m8n8.x4.shared.b16 {%0,%1,%2,%3}, [%4];"
                 : "=r"(r0), "=r"(r1), "=r"(r2), "=r"(r3) : "r"(addr));
}
__device__ __forceinline__ void mma16816(float* c, const uint32_t* a, uint32_t b0, uint32_t b1)
{
    asm volatile(
        "mma.sync.aligned.m16n8k16.row.col.f32.f16.f16.f32 "
        "{%0,%1,%2,%3},{%4,%5,%6,%7},{%8,%9},{%0,%1,%2,%3};"
        : "+f"(c[0]), "+f"(c[1]), "+f"(c[2]), "+f"(c[3])
        : "r"(a[0]), "r"(a[1]), "r"(a[2]), "r"(a[3]), "r"(b0), "r"(b1));
}
__device__ __forceinline__ void cp16(uint32_t dst, const void* src)
{
    asm volatile("cp.async.cg.shared.global [%0], [%1], 16;" :: "r"(dst), "l"(src) : "memory");
}
__device__ __forceinline__ float tanha(float x) {
    float y; asm("tanh.approx.f32 %0, %1;" : "=f"(y) : "f"(x)); return y;
}
// paired tanh on the f16x2 MUFU path
__device__ __forceinline__ float2 tanh2(float a, float b) {
    __half2 u = __floats2half2_rn(a, b);
    uint32_t uin = *(uint32_t*)&u, r;
    asm("tanh.approx.f16x2 %0, %1;" : "=r"(r) : "r"(uin));
    __half2 t = *(__half2*)&r;
    return make_float2(__half2float(t.x), __half2float(t.y));
}
// paired sigmoid: sig(v) = 0.5*tanh(0.5 v)+0.5
__device__ __forceinline__ float2 sig2(float a, float b) {
    float2 t = tanh2(0.5f * a, 0.5f * b);
    return make_float2(fmaf(t.x, 0.5f, 0.5f), fmaf(t.y, 0.5f, 0.5f));
}

// 512B-row tiles (256 halves): byte addr with XOR swizzle
__device__ __forceinline__ uint32_t swz512(int r, int seg) {   // seg = 16B unit, 0..31
    return (uint32_t)(r * 512 + ((seg ^ (r & 7)) << 4));
}
// 256B-row tiles (128 halves)
__device__ __forceinline__ uint32_t swz256(int r, int seg) {   // seg 0..15
    return (uint32_t)(r * 256 + ((seg ^ (r & 7)) << 4));
}

extern __shared__ char smem[];

// --------------------------------------------------------------------------
// Fused kernel. 256 threads = 8 warps in 4(M) x 2(N); warp tile 16x32.
// --------------------------------------------------------------------------
__global__ __launch_bounds__(256, 2) void lstm_fused(
    const float* __restrict__ x, const float* __restrict__ h_,
    const float* __restrict__ c_,
    const float* __restrict__ bz, const float* __restrict__ bi,
    const float* __restrict__ bf, const float* __restrict__ bo,
    const float* __restrict__ bout,
    float* __restrict__ outC, float* __restrict__ outH, float* __restrict__ outY)
{
    const int tid  = threadIdx.x, lane = tid & 31;
    const int warp = tid >> 5;
    const int warpM = warp >> 1, warpN = warp & 1;
    const int row0 = blockIdx.x * 64;

    const uint32_t sbase = (uint32_t)__cvta_generic_to_shared(smem);

    // ---- prefetch chunk 0 ----
    for (int i = tid; i < 2048; i += 256) {            // 64 rows x 32 segs
        int r = i >> 5, seg = i & 31;
        cp16(sbase + BS_OFF(0) + swz512(r, seg), g_W16r + r * 256 + seg * 8);
    }
    asm volatile("cp.async.commit_group;" ::: "memory");

    // ---- As: xh fp32 -> fp16 (cols 0-127 = x, 128-255 = h_) ----
    for (int i = tid; i < 2048; i += 256) {
        int r = i >> 5, seg = i & 31;
        const float* src = (seg < 16) ? (x  + (size_t)(row0 + r) * 128 + seg * 8)
                                      : (h_ + (size_t)(row0 + r) * 128 + (seg - 16) * 8);
        float4 v0 = ((const float4*)src)[0], v1 = ((const float4*)src)[1];
        __half2 h0 = __floats2half2_rn(v0.x, v0.y), h1 = __floats2half2_rn(v0.z, v0.w);
        __half2 h2 = __floats2half2_rn(v1.x, v1.y), h3 = __floats2half2_rn(v1.z, v1.w);
        uint4 pk;
        pk.x = *(uint32_t*)&h0; pk.y = *(uint32_t*)&h1;
        pk.z = *(uint32_t*)&h2; pk.w = *(uint32_t*)&h3;
        *(uint4*)(smem + AS_OFF + swz512(r, seg)) = pk;
    }

    // ldmatrix lane address components
    const int a_row  = warpM * 16 + (lane & 15);
    const int a_segk = (lane >> 4);
    const int b_nloc = ((lane >> 4) & 1) * 8 + (lane & 7);
    const int b_segk = (lane >> 3) & 1;

    __syncthreads();   // As visible

    // ---- preload ALL A fragments into registers ----
    uint32_t afr[16][4];
    {
        const uint32_t as0 = sbase + AS_OFF;
        #pragma unroll
        for (int ks = 0; ks < 16; ks++)
            ldsm_x4(as0 + swz512(a_row, ks * 2 + a_segk),
                    afr[ks][0], afr[ks][1], afr[ks][2], afr[ks][3]);
    }

    // per-thread epilogue constants
    const int colq  = warpN * 8 + 2 * (lane & 3);        // col within chunk's 16
    const int rbase = warpM * 16 + (lane >> 2);
    const int hsegN = warpN;

    float accA[4][4], accB[4][4];                        // ping-pong accumulators

    // ============= GEMM1 + deferred LSTM epilogue, 8 chunks =============
    #pragma unroll
    for (int c = 0; c < 8; c++) {
        float (*accC)[4] = (c & 1) ? accB : accA;        // current
        float (*accP)[4] = (c & 1) ? accA : accB;        // previous (chunk c-1)

        __syncthreads();   // all warps past MMA(c-1): buf[(c+1)&1] reusable
        if (c < 7) {
            const int nb = (c + 1) & 1;
            for (int i = tid; i < 2048; i += 256) {
                int r = i >> 5, seg = i & 31;
                cp16(sbase + BS_OFF(nb) + swz512(r, seg),
                     g_W16r + (size_t)(c + 1) * 16384 + r * 256 + seg * 8);
            }
        } else {
            for (int i = tid; i < 2048; i += 256) {      // w_out -> buf0
                int r = i >> 4, seg = i & 15;
                cp16(sbase + BS_OFF(0) + swz256(r, seg), g_wout16 + r * 128 + seg * 8);
            }
        }
        asm volatile("cp.async.commit_group;" ::: "memory");

        // ---- deferred epilogue of chunk c-1 (overlaps cp.async arrival) ----
        if (c >= 1) {
            const int pc   = c - 1;
            const int colb = pc * 16 + colq;
            const float2 vz = __ldg((const float2*)(bz + colb));
            const float2 vi = __ldg((const float2*)(bi + colb));
            const float2 vf = __ldg((const float2*)(bf + colb));
            const float2 vo = __ldg((const float2*)(bo + colb));
            const int hseg = pc * 2 + hsegN;
            #pragma unroll
            for (int rh = 0; rh < 2; rh++) {
                const int rloc = rbase + rh * 8;
                const int row  = row0 + rloc;
                const float2 cold = __ldg((const float2*)(c_ + (size_t)row * 128 + colb));
                float2 z  = tanh2(accP[0][rh*2+0] + vz.x, accP[0][rh*2+1] + vz.y);
                float2 si = sig2 (accP[1][rh*2+0] + vi.x, accP[1][rh*2+1] + vi.y);
                float2 sf = sig2 (accP[2][rh*2+0] + vf.x, accP[2][rh*2+1] + vf.y);
                float2 so = sig2 (accP[3][rh*2+0] + vo.x, accP[3][rh*2+1] + vo.y);
                float c0 = fmaf(sf.x, cold.x, si.x * z.x);
                float c1 = fmaf(sf.y, cold.y, si.y * z.y);
                float h0 = so.x * tanha(c0);
                float h1 = so.y * tanha(c1);
                *(float2*)(outC + (size_t)row * 128 + colb) = make_float2(c0, c1);
                *(float2*)(outH + (size_t)row * 128 + colb) = make_float2(h0, h1);
                *(__half2*)(smem + HT_OFF + swz256(rloc, hseg) + (colb & 7) * 2) =
                    __floats2half2_rn(h0, h1);
            }
        }

        asm volatile("cp.async.wait_group 1;" ::: "memory");   // chunk c arrived
        __syncthreads();

        #pragma unroll
        for (int nt = 0; nt < 4; nt++)
            #pragma unroll
            for (int r = 0; r < 4; r++) accC[nt][r] = 0.f;

        const uint32_t bs0 = sbase + BS_OFF(c & 1);
        #pragma unroll
        for (int ks = 0; ks < 16; ks++) {
            uint32_t bb[2][4];
            #pragma unroll
            for (int ntp = 0; ntp < 2; ntp++)
                ldsm_x4(bs0 + swz512(warpN * 32 + ntp * 16 + b_nloc, ks * 2 + b_segk),
                        bb[ntp][0], bb[ntp][1], bb[ntp][2], bb[ntp][3]);
            #pragma unroll
            for (int nt = 0; nt < 4; nt++) {
                const int ntp = nt >> 1, hi = nt & 1;
                mma16816(accC[nt], afr[ks], bb[ntp][hi * 2], bb[ntp][hi * 2 + 1]);
            }
        }
    }

    // ---- epilogue of chunk 7 ----
    {
        float (*accP)[4] = accB;                          // chunk 7 -> accB (7&1=1)
        const int colb = 7 * 16 + colq;
        const float2 vz = __ldg((const float2*)(bz + colb));
        const float2 vi = __ldg((const float2*)(bi + colb));
        const float2 vf = __ldg((const float2*)(bf + colb));
        const float2 vo = __ldg((const float2*)(bo + colb));
        const int hseg = 7 * 2 + hsegN;
        #pragma unroll
        for (int rh = 0; rh < 2; rh++) {
            const int rloc = rbase + rh * 8;
            const int row  = row0 + rloc;
            const float2 cold = __ldg((const float2*)(c_ + (size_t)row * 128 + colb));
            float2 z  = tanh2(accP[0][rh*2+0] + vz.x, accP[0][rh*2+1] + vz.y);
            float2 si = sig2 (accP[1][rh*2+0] + vi.x, accP[1][rh*2+1] + vi.y);
            float2 sf = sig2 (accP[2][rh*2+0] + vf.x, accP[2][rh*2+1] + vf.y);
            float2 so = sig2 (accP[3][rh*2+0] + vo.x, accP[3][rh*2+1] + vo.y);
            float c0 = fmaf(sf.x, cold.x, si.x * z.x);
            float c1 = fmaf(sf.y, cold.y, si.y * z.y);
            float h0 = so.x * tanha(c0);
            float h1 = so.y * tanha(c1);
            *(float2*)(outC + (size_t)row * 128 + colb) = make_float2(c0, c1);
            *(float2*)(outH + (size_t)row * 128 + colb) = make_float2(h0, h1);
            *(__half2*)(smem + HT_OFF + swz256(rloc, hseg) + (colb & 7) * 2) =
                __floats2half2_rn(h0, h1);
        }
    }

    asm volatile("cp.async.wait_group 0;" ::: "memory");   // w_out arrived
    __syncthreads();                                       // htile + w_out visible

    // =================== GEMM2: y = sigmoid(h @ w_out^T + b_out) ==========
    float acc2[8][4];
    #pragma unroll
    for (int nt = 0; nt < 8; nt++)
        #pragma unroll
        for (int r = 0; r < 4; r++) acc2[nt][r] = 0.f;

    const uint32_t ht0 = sbase + HT_OFF;
    const uint32_t wo0 = sbase + BS_OFF(0);
    #pragma unroll
    for (int ks = 0; ks < 8; ks++) {
        uint32_t a[4];
        ldsm_x4(ht0 + swz256(a_row, ks * 2 + a_segk), a[0], a[1], a[2], a[3]);
        uint32_t bb[4][4];
        #pragma unroll
        for (int ntp = 0; ntp < 4; ntp++)
            ldsm_x4(wo0 + swz256(warpN * 64 + ntp * 16 + b_nloc, ks * 2 + b_segk),
                    bb[ntp][0], bb[ntp][1], bb[ntp][2], bb[ntp][3]);
        #pragma unroll
        for (int nt = 0; nt < 8; nt++) {
            const int ntp = nt >> 1, hi = nt & 1;
            mma16816(acc2[nt], a, bb[ntp][hi * 2], bb[ntp][hi * 2 + 1]);
        }
    }

    #pragma unroll
    for (int nt = 0; nt < 8; nt++) {
        const int col = warpN * 64 + nt * 8 + 2 * (lane & 3);
        const float2 vb = __ldg((const float2*)(bout + col));
        #pragma unroll
        for (int rh = 0; rh < 2; rh++) {
            const int row = row0 + warpM * 16 + (lane >> 2) + rh * 8;
            float2 v = sig2(acc2[nt][rh * 2 + 0] + vb.x,
                            acc2[nt][rh * 2 + 1] + vb.y);
            *(float2*)(outY + (size_t)row * 128 + col) = v;
        }
    }
}

// --------------------------------------------------------------------------
// Launch
// --------------------------------------------------------------------------
extern "C" void kernel_launch(void* const* d_in, const int* in_sizes, int n_in,
                              void* d_out, int out_size)
{
    const float* c_    = (const float*)d_in[0];
    const float* h_    = (const float*)d_in[1];
    const float* x     = (const float*)d_in[2];
    const float* w     = (const float*)d_in[3];
    const float* wi    = (const float*)d_in[4];
    const float* wf    = (const float*)d_in[5];
    const float* wo    = (const float*)d_in[6];
    const float* w_out = (const float*)d_in[7];
    const float* b     = (const float*)d_in[8];
    const float* bi    = (const float*)d_in[9];
    const float* bf    = (const float*)d_in[10];
    const float* bo    = (const float*)d_in[11];
    const float* b_out = (const float*)d_in[12];

    const int B = in_sizes[0] / 128;
    const size_t BC = (size_t)B * 128;
    float* outC = (float*)d_out;
    float* outH = outC + BC;
    float* outY = outH + BC;

    cudaFuncSetAttribute(lstm_fused, cudaFuncAttributeMaxDynamicSharedMemorySize, SMEM_TOT);

    prep_weights<<<64, 256>>>(w, wi, wf, wo, w_out);
    lstm_fused<<<B / 64, 256, SMEM_TOT>>>(x, h_, c_, b, bi, bf, bo, b_out,
                                          outC, outH, outY);
}

// round 8
// speedup vs baseline: 1.4300x; 1.0651x over previous
#include <cuda_runtime.h>
#include <cuda_fp16.h>
#include <cstdint>

// ===========================================================================
// Fused LSTM cell, mma.sync, 2 CTAs/SM, 2-chunk-interleaved MMA:
// each main iteration loads TWO weight chunks (64KB) and runs their MMAs
// interleaved -> 8 independent accumulator chains (2x mma ILP). A read from
// smem per ks (no A-register bank -> ~40 free regs for ptxas ldsm pipelining).
// Deferred epilogue of the previous pair overlaps cp.async arrival.
// d_out = [c | h | y], each B*128 fp32.
// ===========================================================================

#define AS_OFF    0
#define BS_OFF(i) (32768 + (i) * 32768)
#define HT_OFF    98304
#define SMEM_TOT  114688

__device__ __half g_W16r[512 * 256];    // gate-interleaved stacked weights, fp16
__device__ __half g_wout16[128 * 128];  // w_out, fp16

// --------------------------------------------------------------------------
// K0: convert weights. N-chunks of 64 rows:
//   chunk k (0..7): rows = [warpN0: z(8),i(8),f(8),o(8) | warpN1: same]
// --------------------------------------------------------------------------
__global__ void prep_weights(const float* __restrict__ w,  const float* __restrict__ wi,
                             const float* __restrict__ wf, const float* __restrict__ wo,
                             const float* __restrict__ w_out)
{
    for (int idx = blockIdx.x * blockDim.x + threadIdx.x; idx < 512 * 256;
         idx += gridDim.x * blockDim.x) {
        int dstrow = idx >> 8, kk = idx & 255;
        int chunk = dstrow >> 6, r = dstrow & 63;
        int grp = r >> 5, gate = (r >> 3) & 3, sub = r & 7;
        int gc = chunk * 16 + grp * 8 + sub;
        const float* src = (gate == 0) ? w : (gate == 1) ? wi : (gate == 2) ? wf : wo;
        g_W16r[idx] = __float2half_rn(src[gc * 256 + kk]);
    }
    for (int idx = blockIdx.x * blockDim.x + threadIdx.x; idx < 128 * 128;
         idx += gridDim.x * blockDim.x)
        g_wout16[idx] = __float2half_rn(w_out[idx]);
}

// --------------------------------------------------------------------------
// helpers
// --------------------------------------------------------------------------
__device__ __forceinline__ void ldsm_x4(uint32_t addr, uint32_t& r0, uint32_t& r1,
                                        uint32_t& r2, uint32_t& r3)
{
    asm volatile("ldmatrix.sync.aligned.m8n8.x4.shared.b16 {%0,%1,%2,%3}, [%4];"
                 : "=r"(r0), "=r"(r1), "=r"(r2), "=r"(r3) : "r"(addr));
}
__device__ __forceinline__ void mma16816(float* c, const uint32_t* a, uint32_t b0, uint32_t b1)
{
    asm volatile(
        "mma.sync.aligned.m16n8k16.row.col.f32.f16.f16.f32 "
        "{%0,%1,%2,%3},{%4,%5,%6,%7},{%8,%9},{%0,%1,%2,%3};"
        : "+f"(c[0]), "+f"(c[1]), "+f"(c[2]), "+f"(c[3])
        : "r"(a[0]), "r"(a[1]), "r"(a[2]), "r"(a[3]), "r"(b0), "r"(b1));
}
__device__ __forceinline__ void cp16(uint32_t dst, const void* src)
{
    asm volatile("cp.async.cg.shared.global [%0], [%1], 16;" :: "r"(dst), "l"(src) : "memory");
}
__device__ __forceinline__ float tanha(float x) {
    float y; asm("tanh.approx.f32 %0, %1;" : "=f"(y) : "f"(x)); return y;
}
__device__ __forceinline__ float2 tanh2(float a, float b) {
    __half2 u = __floats2half2_rn(a, b);
    uint32_t uin = *(uint32_t*)&u, r;
    asm("tanh.approx.f16x2 %0, %1;" : "=r"(r) : "r"(uin));
    __half2 t = *(__half2*)&r;
    return make_float2(__half2float(t.x), __half2float(t.y));
}
__device__ __forceinline__ float2 sig2(float a, float b) {
    float2 t = tanh2(0.5f * a, 0.5f * b);
    return make_float2(fmaf(t.x, 0.5f, 0.5f), fmaf(t.y, 0.5f, 0.5f));
}
__device__ __forceinline__ uint32_t swz512(int r, int seg) {   // 512B rows, seg=16B
    return (uint32_t)(r * 512 + ((seg ^ (r & 7)) << 4));
}
__device__ __forceinline__ uint32_t swz256(int r, int seg) {   // 256B rows
    return (uint32_t)(r * 256 + ((seg ^ (r & 7)) << 4));
}

extern __shared__ char smem[];

// --------------------------------------------------------------------------
// Fused kernel. 256 threads = 8 warps in 4(M) x 2(N); warp tile 16x32 per chunk.
// --------------------------------------------------------------------------
__global__ __launch_bounds__(256, 2) void lstm_fused(
    const float* __restrict__ x, const float* __restrict__ h_,
    const float* __restrict__ c_,
    const float* __restrict__ bz, const float* __restrict__ bi,
    const float* __restrict__ bf, const float* __restrict__ bo,
    const float* __restrict__ bout,
    float* __restrict__ outC, float* __restrict__ outH, float* __restrict__ outY)
{
    const int tid  = threadIdx.x, lane = tid & 31;
    const int warp = tid >> 5;
    const int warpM = warp >> 1, warpN = warp & 1;
    const int row0 = blockIdx.x * 64;

    const uint32_t sbase = (uint32_t)__cvta_generic_to_shared(smem);

    // ---- prologue: cp.async chunk pair 0 (chunks 0,1 -> Bs0,Bs1) ----
    for (int i = tid; i < 4096; i += 256) {
        int buf = i >> 11, r = (i >> 5) & 63, seg = i & 31;
        cp16(sbase + BS_OFF(buf) + swz512(r, seg),
             g_W16r + (size_t)buf * 16384 + r * 256 + seg * 8);
    }
    asm volatile("cp.async.commit_group;" ::: "memory");

    // ---- As: xh fp32 -> fp16 (cols 0-127 = x, 128-255 = h_) ----
    for (int i = tid; i < 2048; i += 256) {
        int r = i >> 5, seg = i & 31;
        const float* src = (seg < 16) ? (x  + (size_t)(row0 + r) * 128 + seg * 8)
                                      : (h_ + (size_t)(row0 + r) * 128 + (seg - 16) * 8);
        float4 v0 = ((const float4*)src)[0], v1 = ((const float4*)src)[1];
        __half2 h0 = __floats2half2_rn(v0.x, v0.y), h1 = __floats2half2_rn(v0.z, v0.w);
        __half2 h2 = __floats2half2_rn(v1.x, v1.y), h3 = __floats2half2_rn(v1.z, v1.w);
        uint4 pk;
        pk.x = *(uint32_t*)&h0; pk.y = *(uint32_t*)&h1;
        pk.z = *(uint32_t*)&h2; pk.w = *(uint32_t*)&h3;
        *(uint4*)(smem + AS_OFF + swz512(r, seg)) = pk;
    }

    // lane address components
    const int a_row  = warpM * 16 + (lane & 15);
    const int a_segk = (lane >> 4);
    const int b_nloc = ((lane >> 4) & 1) * 8 + (lane & 7);
    const int b_segk = (lane >> 3) & 1;
    const int colq   = warpN * 8 + 2 * (lane & 3);
    const int rbase  = warpM * 16 + (lane >> 2);

    float accA[4][4], accB[4][4];   // chunk 2j / 2j+1 accumulators

    // ============= 4 iterations of chunk PAIRS =============
    #pragma unroll
    for (int j = 0; j < 4; j++) {
        // ---- deferred epilogue of pair j-1 (overlaps pair j arrival) ----
        if (j > 0) {
            #pragma unroll
            for (int half = 0; half < 2; half++) {
                float (*acc)[4] = half ? accB : accA;
                const int cc   = (j - 1) * 2 + half;
                const int colb = cc * 16 + colq;
                const float2 vz = __ldg((const float2*)(bz + colb));
                const float2 vi = __ldg((const float2*)(bi + colb));
                const float2 vf = __ldg((const float2*)(bf + colb));
                const float2 vo = __ldg((const float2*)(bo + colb));
                const int hseg = cc * 2 + warpN;
                #pragma unroll
                for (int rh = 0; rh < 2; rh++) {
                    const int rloc = rbase + rh * 8;
                    const int row  = row0 + rloc;
                    const float2 cold = __ldg((const float2*)(c_ + (size_t)row * 128 + colb));
                    float2 z  = tanh2(acc[0][rh*2+0] + vz.x, acc[0][rh*2+1] + vz.y);
                    float2 si = sig2 (acc[1][rh*2+0] + vi.x, acc[1][rh*2+1] + vi.y);
                    float2 sf = sig2 (acc[2][rh*2+0] + vf.x, acc[2][rh*2+1] + vf.y);
                    float2 so = sig2 (acc[3][rh*2+0] + vo.x, acc[3][rh*2+1] + vo.y);
                    float c0 = fmaf(sf.x, cold.x, si.x * z.x);
                    float c1 = fmaf(sf.y, cold.y, si.y * z.y);
                    float h0 = so.x * tanha(c0);
                    float h1 = so.y * tanha(c1);
                    *(float2*)(outC + (size_t)row * 128 + colb) = make_float2(c0, c1);
                    *(float2*)(outH + (size_t)row * 128 + colb) = make_float2(h0, h1);
                    *(__half2*)(smem + HT_OFF + swz256(rloc, hseg) + (colb & 7) * 2) =
                        __floats2half2_rn(h0, h1);
                }
            }
        }

        asm volatile("cp.async.wait_group 0;" ::: "memory");   // pair j arrived
        __syncthreads();                                       // (also covers As at j=0)

        #pragma unroll
        for (int nt = 0; nt < 4; nt++)
            #pragma unroll
            for (int r = 0; r < 4; r++) { accA[nt][r] = 0.f; accB[nt][r] = 0.f; }

        // ---- interleaved MMA over both chunks: 8 independent acc chains ----
        const uint32_t as0 = sbase + AS_OFF;
        const uint32_t bs0 = sbase + BS_OFF(0);
        const uint32_t bs1 = sbase + BS_OFF(1);
        #pragma unroll
        for (int ks = 0; ks < 16; ks++) {
            uint32_t a[4];
            ldsm_x4(as0 + swz512(a_row, ks * 2 + a_segk), a[0], a[1], a[2], a[3]);
            uint32_t b0[2][4], b1[2][4];
            #pragma unroll
            for (int ntp = 0; ntp < 2; ntp++) {
                const uint32_t off = swz512(warpN * 32 + ntp * 16 + b_nloc, ks * 2 + b_segk);
                ldsm_x4(bs0 + off, b0[ntp][0], b0[ntp][1], b0[ntp][2], b0[ntp][3]);
                ldsm_x4(bs1 + off, b1[ntp][0], b1[ntp][1], b1[ntp][2], b1[ntp][3]);
            }
            #pragma unroll
            for (int nt = 0; nt < 4; nt++) {
                const int ntp = nt >> 1, hi = nt & 1;
                mma16816(accA[nt], a, b0[ntp][hi * 2], b0[ntp][hi * 2 + 1]);
                mma16816(accB[nt], a, b1[ntp][hi * 2], b1[ntp][hi * 2 + 1]);
            }
        }

        __syncthreads();   // all warps done reading Bs0/Bs1

        if (j < 3) {
            // cp.async next pair (chunks 2j+2, 2j+3)
            for (int i = tid; i < 4096; i += 256) {
                int buf = i >> 11, r = (i >> 5) & 63, seg = i & 31;
                cp16(sbase + BS_OFF(buf) + swz512(r, seg),
                     g_W16r + (size_t)(2 * j + 2 + buf) * 16384 + r * 256 + seg * 8);
            }
        } else {
            // w_out -> Bs0 (32KB, swz256 layout)
            for (int i = tid; i < 2048; i += 256) {
                int r = i >> 4, seg = i & 15;
                cp16(sbase + BS_OFF(0) + swz256(r, seg), g_wout16 + r * 128 + seg * 8);
            }
        }
        asm volatile("cp.async.commit_group;" ::: "memory");
    }

    // ---- epilogue of pair 3 (overlaps w_out arrival) ----
    #pragma unroll
    for (int half = 0; half < 2; half++) {
        float (*acc)[4] = half ? accB : accA;
        const int cc   = 6 + half;
        const int colb = cc * 16 + colq;
        const float2 vz = __ldg((const float2*)(bz + colb));
        const float2 vi = __ldg((const float2*)(bi + colb));
        const float2 vf = __ldg((const float2*)(bf + colb));
        const float2 vo = __ldg((const float2*)(bo + colb));
        const int hseg = cc * 2 + warpN;
        #pragma unroll
        for (int rh = 0; rh < 2; rh++) {
            const int rloc = rbase + rh * 8;
            const int row  = row0 + rloc;
            const float2 cold = __ldg((const float2*)(c_ + (size_t)row * 128 + colb));
            float2 z  = tanh2(acc[0][rh*2+0] + vz.x, acc[0][rh*2+1] + vz.y);
            float2 si = sig2 (acc[1][rh*2+0] + vi.x, acc[1][rh*2+1] + vi.y);
            float2 sf = sig2 (acc[2][rh*2+0] + vf.x, acc[2][rh*2+1] + vf.y);
            float2 so = sig2 (acc[3][rh*2+0] + vo.x, acc[3][rh*2+1] + vo.y);
            float c0 = fmaf(sf.x, cold.x, si.x * z.x);
            float c1 = fmaf(sf.y, cold.y, si.y * z.y);
            float h0 = so.x * tanha(c0);
            float h1 = so.y * tanha(c1);
            *(float2*)(outC + (size_t)row * 128 + colb) = make_float2(c0, c1);
            *(float2*)(outH + (size_t)row * 128 + colb) = make_float2(h0, h1);
            *(__half2*)(smem + HT_OFF + swz256(rloc, hseg) + (colb & 7) * 2) =
                __floats2half2_rn(h0, h1);
        }
    }

    asm volatile("cp.async.wait_group 0;" ::: "memory");   // w_out arrived
    __syncthreads();                                       // htile + w_out visible

    // =================== GEMM2: y = sigmoid(h @ w_out^T + b_out) ==========
    float acc2[8][4];
    #pragma unroll
    for (int nt = 0; nt < 8; nt++)
        #pragma unroll
        for (int r = 0; r < 4; r++) acc2[nt][r] = 0.f;

    const uint32_t ht0 = sbase + HT_OFF;
    const uint32_t wo0 = sbase + BS_OFF(0);
    #pragma unroll
    for (int ks = 0; ks < 8; ks++) {
        uint32_t a[4];
        ldsm_x4(ht0 + swz256(warpM * 16 + (lane & 15), ks * 2 + a_segk), a[0], a[1], a[2], a[3]);
        uint32_t bb[4][4];
        #pragma unroll
        for (int ntp = 0; ntp < 4; ntp++)
            ldsm_x4(wo0 + swz256(warpN * 64 + ntp * 16 + b_nloc, ks * 2 + b_segk),
                    bb[ntp][0], bb[ntp][1], bb[ntp][2], bb[ntp][3]);
        #pragma unroll
        for (int nt = 0; nt < 8; nt++) {
            const int ntp = nt >> 1, hi = nt & 1;
            mma16816(acc2[nt], a, bb[ntp][hi * 2], bb[ntp][hi * 2 + 1]);
        }
    }

    #pragma unroll
    for (int nt = 0; nt < 8; nt++) {
        const int col = warpN * 64 + nt * 8 + 2 * (lane & 3);
        const float2 vb = __ldg((const float2*)(bout + col));
        #pragma unroll
        for (int rh = 0; rh < 2; rh++) {
            const int row = row0 + warpM * 16 + (lane >> 2) + rh * 8;
            float2 v = sig2(acc2[nt][rh * 2 + 0] + vb.x,
                            acc2[nt][rh * 2 + 1] + vb.y);
            *(float2*)(outY + (size_t)row * 128 + col) = v;
        }
    }
}

// --------------------------------------------------------------------------
// Launch
// --------------------------------------------------------------------------
extern "C" void kernel_launch(void* const* d_in, const int* in_sizes, int n_in,
                              void* d_out, int out_size)
{
    const float* c_    = (const float*)d_in[0];
    const float* h_    = (const float*)d_in[1];
    const float* x     = (const float*)d_in[2];
    const float* w     = (const float*)d_in[3];
    const float* wi    = (const float*)d_in[4];
    const float* wf    = (const float*)d_in[5];
    const float* wo    = (const float*)d_in[6];
    const float* w_out = (const float*)d_in[7];
    const float* b     = (const float*)d_in[8];
    const float* bi    = (const float*)d_in[9];
    const float* bf    = (const float*)d_in[10];
    const float* bo    = (const float*)d_in[11];
    const float* b_out = (const float*)d_in[12];

    const int B = in_sizes[0] / 128;
    const size_t BC = (size_t)B * 128;
    float* outC = (float*)d_out;
    float* outH = outC + BC;
    float* outY = outH + BC;

    cudaFuncSetAttribute(lstm_fused, cudaFuncAttributeMaxDynamicSharedMemorySize, SMEM_TOT);

    prep_weights<<<64, 256>>>(w, wi, wf, wo, w_out);
    lstm_fused<<<B / 64, 256, SMEM_TOT>>>(x, h_, c_, b, bi, bf, bo, b_out,
                                          outC, outH, outY);
}